// round 16
// baseline (speedup 1.0000x reference)
#include <cuda_runtime.h>
#include <math_constants.h>

#define K_LEN 1024
#define I_LEN 8192
#define DIM   128
#define FULLM 0xffffffffu

#define NB   128     // row bands (CTAs, ONE warp each)
#define BR   8       // rows per band
#define NCH  32      // column chunks
#define CW   256     // columns per chunk (32 lanes x 8 cols)

// Scratch (alloc-free rule: __device__ globals)
__device__ float g_C[K_LEN * I_LEN];       // 32 MB cost matrix
__device__ float g_k2[K_LEN];
__device__ float g_x2[I_LEN];
__device__ float g_row[NB][I_LEN];         // bottom-row D of each band (4 MB)
__device__ unsigned g_flag[NB][NCH];       // chunk-done flags

// ---------------------------------------------------------------------------
// Kernel 1: squared row norms + zero the wavefront flags.
// ---------------------------------------------------------------------------
__global__ void norms_kernel(const float* __restrict__ kern,
                             const float* __restrict__ x) {
    int gtid = blockIdx.x * blockDim.x + threadIdx.x;
    if (gtid < NB * NCH) ((unsigned*)g_flag)[gtid] = 0u;

    int warp = gtid >> 5;
    int lane = threadIdx.x & 31;
    if (warp >= K_LEN + I_LEN) return;
    const float* row = (warp < K_LEN) ? (kern + warp * DIM)
                                      : (x + (warp - K_LEN) * DIM);
    float4 v = ((const float4*)row)[lane];
    float s = v.x * v.x + v.y * v.y + v.z * v.z + v.w * v.w;
#pragma unroll
    for (int off = 16; off; off >>= 1) s += __shfl_xor_sync(FULLM, s, off);
    if (lane == 0) {
        if (warp < K_LEN) g_k2[warp] = s;
        else              g_x2[warp - K_LEN] = s;
    }
}

// ---------------------------------------------------------------------------
// Kernel 2: C[m][n] = max(k2[m] + x2[n] - 2*<kern_m, x_n>, 0)   (R7 version)
// ---------------------------------------------------------------------------
#define BM 128
#define BN 128
#define BK 8

__global__ __launch_bounds__(256, 2) void cost_gemm(const float* __restrict__ A,
                                                    const float* __restrict__ B) {
    __shared__ float As[2][BK][BM + 4];
    __shared__ float Bs[2][BK][BN + 4];
    const int tid = threadIdx.x;
    const int m0 = blockIdx.y * BM;
    const int n0 = blockIdx.x * BN;
    const int lr = tid >> 1;
    const int lc = (tid & 1) * 4;
    const int tx = tid & 15;
    const int ty = tid >> 4;

    float acc[8][8];
#pragma unroll
    for (int i = 0; i < 8; i++)
#pragma unroll
        for (int j = 0; j < 8; j++) acc[i][j] = 0.0f;

    {
        float4 va = *(const float4*)(A + (size_t)(m0 + lr) * DIM + lc);
        float4 vb = *(const float4*)(B + (size_t)(n0 + lr) * DIM + lc);
        As[0][lc + 0][lr] = va.x; As[0][lc + 1][lr] = va.y;
        As[0][lc + 2][lr] = va.z; As[0][lc + 3][lr] = va.w;
        Bs[0][lc + 0][lr] = vb.x; Bs[0][lc + 1][lr] = vb.y;
        Bs[0][lc + 2][lr] = vb.z; Bs[0][lc + 3][lr] = vb.w;
    }
    __syncthreads();

    int buf = 0;
    for (int k0 = 0; k0 < DIM; k0 += BK) {
        const bool has_next = (k0 + BK < DIM);
        float4 na, nb;
        if (has_next) {
            na = *(const float4*)(A + (size_t)(m0 + lr) * DIM + k0 + BK + lc);
            nb = *(const float4*)(B + (size_t)(n0 + lr) * DIM + k0 + BK + lc);
        }
#pragma unroll
        for (int k = 0; k < BK; k++) {
            float a[8], b[8];
            *(float4*)(a)     = *(const float4*)&As[buf][k][ty * 8];
            *(float4*)(a + 4) = *(const float4*)&As[buf][k][ty * 8 + 4];
            *(float4*)(b)     = *(const float4*)&Bs[buf][k][tx * 8];
            *(float4*)(b + 4) = *(const float4*)&Bs[buf][k][tx * 8 + 4];
#pragma unroll
            for (int i = 0; i < 8; i++)
#pragma unroll
                for (int j = 0; j < 8; j++)
                    acc[i][j] += a[i] * b[j];
        }
        if (has_next) {
            const int nbuf = buf ^ 1;
            As[nbuf][lc + 0][lr] = na.x; As[nbuf][lc + 1][lr] = na.y;
            As[nbuf][lc + 2][lr] = na.z; As[nbuf][lc + 3][lr] = na.w;
            Bs[nbuf][lc + 0][lr] = nb.x; Bs[nbuf][lc + 1][lr] = nb.y;
            Bs[nbuf][lc + 2][lr] = nb.z; Bs[nbuf][lc + 3][lr] = nb.w;
            __syncthreads();
            buf = nbuf;
        }
    }

    float x2v[8];
#pragma unroll
    for (int j = 0; j < 8; j++) x2v[j] = g_x2[n0 + tx * 8 + j];
#pragma unroll
    for (int i = 0; i < 8; i++) {
        const int m = m0 + ty * 8 + i;
        const float k2 = g_k2[m];
        float4 o0, o1;
        o0.x = fmaxf(k2 + x2v[0] - 2.0f * acc[i][0], 0.0f);
        o0.y = fmaxf(k2 + x2v[1] - 2.0f * acc[i][1], 0.0f);
        o0.z = fmaxf(k2 + x2v[2] - 2.0f * acc[i][2], 0.0f);
        o0.w = fmaxf(k2 + x2v[3] - 2.0f * acc[i][3], 0.0f);
        o1.x = fmaxf(k2 + x2v[4] - 2.0f * acc[i][4], 0.0f);
        o1.y = fmaxf(k2 + x2v[5] - 2.0f * acc[i][5], 0.0f);
        o1.z = fmaxf(k2 + x2v[6] - 2.0f * acc[i][6], 0.0f);
        o1.w = fmaxf(k2 + x2v[7] - 2.0f * acc[i][7], 0.0f);
        float* dst = g_C + (size_t)m * I_LEN + n0 + tx * 8;
        *(float4*)(dst)     = o0;
        *(float4*)(dst + 4) = o1;
    }
}

// ---------------------------------------------------------------------------
// Kernel 3: block-wavefront DTW DP, ONE WARP per CTA.
// CTA b owns rows [8b, 8b+8); chunks of 256 cols (8 per lane), left->right.
// Per row: shfl dleft, e-phase + local (C,E) prefix, 5-level warp pair-scan,
// exclusive shfl, parallel apply via local prefixes. No __syncthreads at all;
// chunk carry Dl[2][BR] in smem guarded by __syncwarp. Cross-CTA: per-chunk
// release/acquire flag + g_row boundary rows (read via __ldcg = L2).
// ---------------------------------------------------------------------------
__global__ __launch_bounds__(32, 1) void dtw_wave(float* __restrict__ out,
                                                  int out_size) {
    __shared__ float Dl[2][BR];      // D at chunk-left-1 per row, ping-pong
    const float INF = CUDART_INF_F;
    const int b    = blockIdx.x;
    const int lane = threadIdx.x;

    if (b == 0)
        for (int i = lane; i < out_size; i += 32)
            if (i > 0) out[i] = 0.0f;
    if (lane < BR) Dl[0][lane] = INF;
    __syncwarp();

    float res = INF;

    for (int j = 0; j < NCH; j++) {
        const int sel = j & 1;
        if (b > 0 && lane == 0) {
            unsigned v;
            do {
                asm volatile("ld.acquire.gpu.global.u32 %0, [%1];"
                             : "=r"(v) : "l"(&g_flag[b - 1][j]));
            } while (!v);
        }
        __syncwarp();

        const int colbase = j * CW + 8 * lane;

        // top boundary (row above the band), via L2 (__ldcg)
        float Dp[8];
        if (b > 0) {
            float4 t0 = __ldcg((const float4*)(&g_row[b - 1][colbase]));
            float4 t1 = __ldcg((const float4*)(&g_row[b - 1][colbase + 4]));
            Dp[0] = t0.x; Dp[1] = t0.y; Dp[2] = t0.z; Dp[3] = t0.w;
            Dp[4] = t1.x; Dp[5] = t1.y; Dp[6] = t1.z; Dp[7] = t1.w;
        } else {
#pragma unroll
            for (int k = 0; k < 8; k++) Dp[k] = INF;
        }
        float lastD7 = Dp[7];

        // top-left diagonal for lane 0, row 0
        float dlc = INF;
        if (lane == 0) {
            if (b > 0) dlc = (j > 0) ? __ldcg(&g_row[b - 1][j * CW - 1]) : INF;
            else       dlc = (j == 0) ? 0.0f : INF;    // D[-1][-1] = 0
        }

        const float* cbase = g_C + (size_t)(b * BR) * I_LEN + colbase;
        float c[8];
        {
            float4 a0 = *(const float4*)(cbase);
            float4 a1 = *(const float4*)(cbase + 4);
            c[0] = a0.x; c[1] = a0.y; c[2] = a0.z; c[3] = a0.w;
            c[4] = a1.x; c[5] = a1.y; c[6] = a1.z; c[7] = a1.w;
        }

#pragma unroll
        for (int r = 0; r < BR; r++) {
            float nx[8];
            if (r + 1 < BR) {
                const float* nrow = cbase + (size_t)(r + 1) * I_LEN;
                float4 a0 = *(const float4*)(nrow);
                float4 a1 = *(const float4*)(nrow + 4);
                nx[0] = a0.x; nx[1] = a0.y; nx[2] = a0.z; nx[3] = a0.w;
                nx[4] = a1.x; nx[5] = a1.y; nx[6] = a1.z; nx[7] = a1.w;
            }

            float dleft = __shfl_up_sync(FULLM, lastD7, 1);
            if (lane == 0) dleft = dlc;

            float e[8];
            e[0] = fminf(dleft, Dp[0]) + c[0];
#pragma unroll
            for (int k = 1; k < 8; k++)
                e[k] = fminf(Dp[k - 1], Dp[k]) + c[k];

            // local inclusive (C,E) prefixes (kept for the parallel apply)
            float pC[8], pE[8];
            pC[0] = c[0]; pE[0] = e[0];
#pragma unroll
            for (int k = 1; k < 8; k++) {
                pE[k] = fminf(pE[k - 1] + c[k], e[k]);
                pC[k] = pC[k - 1] + c[k];
            }
            float Cl = pC[7], El = pE[7];

            // 5-level warp pair-scan
#pragma unroll
            for (int off = 1; off < 32; off <<= 1) {
                float Cu = __shfl_up_sync(FULLM, Cl, off);
                float Eu = __shfl_up_sync(FULLM, El, off);
                if (lane >= off) {
                    El = fminf(Eu + Cl, El);
                    Cl = Cu + Cl;
                }
            }
            float exC = __shfl_up_sync(FULLM, Cl, 1);
            float exE = __shfl_up_sync(FULLM, El, 1);
            if (lane == 0) { exC = 0.0f; exE = INF; }

            float Dlv = Dl[sel][r];                 // D[row][chunk_left - 1]
            float Din = fminf(exE, Dlv + exC);      // D at col 8*lane - 1

            float D[8];
#pragma unroll
            for (int k = 0; k < 8; k++)
                D[k] = fminf(Din + pC[k], pE[k]);

            dlc = Dlv;                               // next row's diag (lane 0)
            lastD7 = D[7];
            if (lane == 31) Dl[sel ^ 1][r] = D[7];   // boundary for next chunk
            if (r == BR - 1) {
                if (b < NB - 1) {
                    *(float4*)(&g_row[b][colbase]) =
                        make_float4(D[0], D[1], D[2], D[3]);
                    *(float4*)(&g_row[b][colbase + 4]) =
                        make_float4(D[4], D[5], D[6], D[7]);
                }
                res = D[7];
            }
#pragma unroll
            for (int k = 0; k < 8; k++) { Dp[k] = D[k]; c[k] = nx[k]; }
        }
        __syncwarp();            // Dl writes visible for next chunk

        if (b < NB - 1) {
            __threadfence();
            if (lane == 0)
                asm volatile("st.release.gpu.global.u32 [%0], %1;"
                             :: "l"(&g_flag[b][j]), "r"(1u));
        }
    }

    if (b == NB - 1 && lane == 31) out[0] = res;
}

// ---------------------------------------------------------------------------
extern "C" void kernel_launch(void* const* d_in, const int* in_sizes, int n_in,
                              void* d_out, int out_size) {
    const float* kern = (const float*)d_in[0];
    const float* x    = (const float*)d_in[1];
    if (n_in >= 2 && in_sizes[0] == I_LEN * DIM && in_sizes[1] == K_LEN * DIM) {
        kern = (const float*)d_in[1];
        x    = (const float*)d_in[0];
    }

    int nwarp_rows = K_LEN + I_LEN;
    norms_kernel<<<(nwarp_rows + 7) / 8, 256>>>(kern, x);

    dim3 grid(I_LEN / BN, K_LEN / BM);
    cost_gemm<<<grid, 256>>>(kern, x);

    dtw_wave<<<NB, 32>>>((float*)d_out, out_size);
}

// round 17
// speedup vs baseline: 6.3145x; 6.3145x over previous
#include <cuda_runtime.h>
#include <math_constants.h>

#define K_LEN 1024
#define I_LEN 8192
#define DIM   128
#define FULLM 0xffffffffu

#define NB   64      // row bands (CTAs)
#define BR   16      // rows per band
#define NCH  16      // column chunks
#define CW   512     // columns per chunk (4 warps x 4 cols/lane)
#define DTH  128     // DP threads per CTA

// Scratch (alloc-free rule: __device__ globals)
__device__ float g_C[K_LEN * I_LEN];       // 32 MB cost matrix
__device__ float g_k2[K_LEN];
__device__ float g_x2[I_LEN];
__device__ float g_row[NB][I_LEN];         // bottom-row D of each band
__device__ unsigned g_flag[NB][NCH];       // chunk-done flags

// ---------------------------------------------------------------------------
// Kernel 1: squared row norms + zero the wavefront flags.
// ---------------------------------------------------------------------------
__global__ void norms_kernel(const float* __restrict__ kern,
                             const float* __restrict__ x) {
    int gtid = blockIdx.x * blockDim.x + threadIdx.x;
    if (gtid < NB * NCH) ((unsigned*)g_flag)[gtid] = 0u;

    int warp = gtid >> 5;
    int lane = threadIdx.x & 31;
    if (warp >= K_LEN + I_LEN) return;
    const float* row = (warp < K_LEN) ? (kern + warp * DIM)
                                      : (x + (warp - K_LEN) * DIM);
    float4 v = ((const float4*)row)[lane];
    float s = v.x * v.x + v.y * v.y + v.z * v.z + v.w * v.w;
#pragma unroll
    for (int off = 16; off; off >>= 1) s += __shfl_xor_sync(FULLM, s, off);
    if (lane == 0) {
        if (warp < K_LEN) g_k2[warp] = s;
        else              g_x2[warp - K_LEN] = s;
    }
}

// ---------------------------------------------------------------------------
// Kernel 2: C[m][n] = max(k2[m] + x2[n] - 2*<kern_m, x_n>, 0)   (R7 version)
// ---------------------------------------------------------------------------
#define BM 128
#define BN 128
#define BK 8

__global__ __launch_bounds__(256, 2) void cost_gemm(const float* __restrict__ A,
                                                    const float* __restrict__ B) {
    __shared__ float As[2][BK][BM + 4];
    __shared__ float Bs[2][BK][BN + 4];
    const int tid = threadIdx.x;
    const int m0 = blockIdx.y * BM;
    const int n0 = blockIdx.x * BN;
    const int lr = tid >> 1;
    const int lc = (tid & 1) * 4;
    const int tx = tid & 15;
    const int ty = tid >> 4;

    float acc[8][8];
#pragma unroll
    for (int i = 0; i < 8; i++)
#pragma unroll
        for (int j = 0; j < 8; j++) acc[i][j] = 0.0f;

    {
        float4 va = *(const float4*)(A + (size_t)(m0 + lr) * DIM + lc);
        float4 vb = *(const float4*)(B + (size_t)(n0 + lr) * DIM + lc);
        As[0][lc + 0][lr] = va.x; As[0][lc + 1][lr] = va.y;
        As[0][lc + 2][lr] = va.z; As[0][lc + 3][lr] = va.w;
        Bs[0][lc + 0][lr] = vb.x; Bs[0][lc + 1][lr] = vb.y;
        Bs[0][lc + 2][lr] = vb.z; Bs[0][lc + 3][lr] = vb.w;
    }
    __syncthreads();

    int buf = 0;
    for (int k0 = 0; k0 < DIM; k0 += BK) {
        const bool has_next = (k0 + BK < DIM);
        float4 na, nb;
        if (has_next) {
            na = *(const float4*)(A + (size_t)(m0 + lr) * DIM + k0 + BK + lc);
            nb = *(const float4*)(B + (size_t)(n0 + lr) * DIM + k0 + BK + lc);
        }
#pragma unroll
        for (int k = 0; k < BK; k++) {
            float a[8], b[8];
            *(float4*)(a)     = *(const float4*)&As[buf][k][ty * 8];
            *(float4*)(a + 4) = *(const float4*)&As[buf][k][ty * 8 + 4];
            *(float4*)(b)     = *(const float4*)&Bs[buf][k][tx * 8];
            *(float4*)(b + 4) = *(const float4*)&Bs[buf][k][tx * 8 + 4];
#pragma unroll
            for (int i = 0; i < 8; i++)
#pragma unroll
                for (int j = 0; j < 8; j++)
                    acc[i][j] += a[i] * b[j];
        }
        if (has_next) {
            const int nbuf = buf ^ 1;
            As[nbuf][lc + 0][lr] = na.x; As[nbuf][lc + 1][lr] = na.y;
            As[nbuf][lc + 2][lr] = na.z; As[nbuf][lc + 3][lr] = na.w;
            Bs[nbuf][lc + 0][lr] = nb.x; Bs[nbuf][lc + 1][lr] = nb.y;
            Bs[nbuf][lc + 2][lr] = nb.z; Bs[nbuf][lc + 3][lr] = nb.w;
            __syncthreads();
            buf = nbuf;
        }
    }

    float x2v[8];
#pragma unroll
    for (int j = 0; j < 8; j++) x2v[j] = g_x2[n0 + tx * 8 + j];
#pragma unroll
    for (int i = 0; i < 8; i++) {
        const int m = m0 + ty * 8 + i;
        const float k2 = g_k2[m];
        float4 o0, o1;
        o0.x = fmaxf(k2 + x2v[0] - 2.0f * acc[i][0], 0.0f);
        o0.y = fmaxf(k2 + x2v[1] - 2.0f * acc[i][1], 0.0f);
        o0.z = fmaxf(k2 + x2v[2] - 2.0f * acc[i][2], 0.0f);
        o0.w = fmaxf(k2 + x2v[3] - 2.0f * acc[i][3], 0.0f);
        o1.x = fmaxf(k2 + x2v[4] - 2.0f * acc[i][4], 0.0f);
        o1.y = fmaxf(k2 + x2v[5] - 2.0f * acc[i][5], 0.0f);
        o1.z = fmaxf(k2 + x2v[6] - 2.0f * acc[i][6], 0.0f);
        o1.w = fmaxf(k2 + x2v[7] - 2.0f * acc[i][7], 0.0f);
        float* dst = g_C + (size_t)m * I_LEN + n0 + tx * 8;
        *(float4*)(dst)     = o0;
        *(float4*)(dst + 4) = o1;
    }
}

// ---------------------------------------------------------------------------
// Kernel 3: block-wavefront DTW DP, TWO ROWS per scan phase.
// Row pair (r = top with costs a/e, r+1 = bottom with costs b). Per-column
// affine (min,+) map on (u,v) = (D_r, D_{r+1}):
//   u_j = min(u_{j-1} + a_j, e_j)
//   v_j = min(v_{j-1} + b_j, u_{j-1} + b_j, e_j + b_j)      (uses a_j >= 0)
// 5-param map f(u,v) = (min(u+A,E1), min(u+B, v+C, E2)), closed under
// composition. One 5-level warp scan + 2 barriers now advance 2 rows.
// Skeleton (tiling, flags, g_row, Dl ping-pong) identical to R12.
// ---------------------------------------------------------------------------
__global__ __launch_bounds__(DTH, 1) void dtw_wave(float* __restrict__ out,
                                                   int out_size) {
    __shared__ float sh_bound[DTH];
    __shared__ float shP[4][5];      // warp-total maps
    __shared__ float Dl[2][BR];      // D at chunk_left-1 per row, ping-pong
    const float INF = CUDART_INF_F;
    const int b    = blockIdx.x;
    const int tid  = threadIdx.x;
    const int lane = tid & 31;
    const int w    = tid >> 5;

    if (b == 0)
        for (int i = tid; i < out_size; i += DTH)
            if (i > 0) out[i] = 0.0f;
    if (tid < BR) Dl[0][tid] = INF;

    float res = INF;

    for (int j = 0; j < NCH; j++) {
        const int sel = j & 1;
        if (b > 0 && tid == 0) {
            unsigned v;
            do {
                asm volatile("ld.acquire.gpu.global.u32 %0, [%1];"
                             : "=r"(v) : "l"(&g_flag[b - 1][j]));
            } while (!v);
        }
        __syncthreads();

        const int colbase = j * CW + 4 * tid;

        // top boundary (row above the band)
        float Dp[4];
        if (b > 0) {
            float4 tv = *(const float4*)(&g_row[b - 1][colbase]);
            Dp[0] = tv.x; Dp[1] = tv.y; Dp[2] = tv.z; Dp[3] = tv.w;
        } else {
            Dp[0] = Dp[1] = Dp[2] = Dp[3] = INF;
        }
        // top-left diagonal for thread 0, row 0 of the band
        float dlc;
        if (b > 0) dlc = (j > 0) ? g_row[b - 1][j * CW - 1] : INF;
        else       dlc = (j == 0) ? 0.0f : INF;   // D[-1][-1] = 0
        sh_bound[tid] = Dp[3];
        __syncthreads();

        const float* cbase = g_C + (size_t)(b * BR) * I_LEN + colbase;
        float4 ca = *(const float4*)cbase;                          // row r
        float4 cb = *(const float4*)(cbase + (size_t)I_LEN);        // row r+1

        for (int r = 0; r < BR; r += 2) {
            float4 ca2, cb2;
            if (r + 2 < BR) {
                ca2 = *(const float4*)(cbase + (size_t)(r + 2) * I_LEN);
                cb2 = *(const float4*)(cbase + (size_t)(r + 3) * I_LEN);
            }

            float dleft = (tid == 0) ? dlc : sh_bound[tid - 1];
            float a0 = ca.x, a1 = ca.y, a2 = ca.z, a3 = ca.w;
            float b0 = cb.x, b1 = cb.y, b2 = cb.z, b3 = cb.w;

            float e[4];
            e[0] = fminf(dleft, Dp[0]) + a0;
            e[1] = fminf(Dp[0], Dp[1]) + a1;
            e[2] = fminf(Dp[1], Dp[2]) + a2;
            e[3] = fminf(Dp[2], Dp[3]) + a3;

            // local inclusive prefix maps P_k over this thread's 4 columns
            float aa[4] = {a0, a1, a2, a3};
            float bbv[4] = {b0, b1, b2, b3};
            float pA[4], pE1[4], pB[4], pC[4], pE2[4];
            pA[0] = aa[0]; pE1[0] = e[0];
            pB[0] = bbv[0]; pC[0] = bbv[0]; pE2[0] = e[0] + bbv[0];
#pragma unroll
            for (int k = 1; k < 4; k++) {
                pB[k]  = fminf(pA[k - 1], pB[k - 1]) + bbv[k];
                pE2[k] = fminf(fminf(pE1[k - 1], pE2[k - 1]), e[k]) + bbv[k];
                pA[k]  = pA[k - 1] + aa[k];
                pE1[k] = fminf(pE1[k - 1] + aa[k], e[k]);
                pC[k]  = pC[k - 1] + bbv[k];
            }

            // warp scan of 5-param maps
            float sA = pA[3], sE1 = pE1[3], sB = pB[3], sC = pC[3], sE2 = pE2[3];
#pragma unroll
            for (int off = 1; off < 32; off <<= 1) {
                float Au  = __shfl_up_sync(FULLM, sA, off);
                float E1u = __shfl_up_sync(FULLM, sE1, off);
                float Bu  = __shfl_up_sync(FULLM, sB, off);
                float Cu  = __shfl_up_sync(FULLM, sC, off);
                float E2u = __shfl_up_sync(FULLM, sE2, off);
                if (lane >= off) {
                    float nA  = Au + sA;
                    float nE1 = fminf(E1u + sA, sE1);
                    float nB  = fminf(Au + sB, Bu + sC);
                    float nC  = Cu + sC;
                    float nE2 = fminf(E1u + sB, fminf(E2u + sC, sE2));
                    sA = nA; sE1 = nE1; sB = nB; sC = nC; sE2 = nE2;
                }
            }
            if (lane == 31) {
                shP[w][0] = sA; shP[w][1] = sE1; shP[w][2] = sB;
                shP[w][3] = sC; shP[w][4] = sE2;
            }
            // lane-exclusive map (identity at lane 0)
            float leA  = __shfl_up_sync(FULLM, sA, 1);
            float leE1 = __shfl_up_sync(FULLM, sE1, 1);
            float leB  = __shfl_up_sync(FULLM, sB, 1);
            float leC  = __shfl_up_sync(FULLM, sC, 1);
            float leE2 = __shfl_up_sync(FULLM, sE2, 1);
            if (lane == 0) { leA = 0.0f; leE1 = INF; leB = INF; leC = 0.0f; leE2 = INF; }
            __syncthreads();

            // warp-prefix map (identity for warp 0)
            float WA = 0.0f, WE1 = INF, WB = INF, WC = 0.0f, WE2 = INF;
#pragma unroll
            for (int k = 0; k < 3; k++) {
                if (k < w) {
                    float kA = shP[k][0], kE1 = shP[k][1], kB = shP[k][2];
                    float kC = shP[k][3], kE2 = shP[k][4];
                    float nA  = WA + kA;
                    float nE1 = fminf(WE1 + kA, kE1);
                    float nB  = fminf(WA + kB, WB + kC);
                    float nC  = WC + kC;
                    float nE2 = fminf(WE1 + kB, fminf(WE2 + kC, kE2));
                    WA = nA; WE1 = nE1; WB = nB; WC = nC; WE2 = nE2;
                }
            }
            // total exclusive: laneExcl ∘ warpPrefix
            float xA  = WA + leA;
            float xE1 = fminf(WE1 + leA, leE1);
            float xB  = fminf(WA + leB, WB + leC);
            float xC  = WC + leC;
            float xE2 = fminf(WE1 + leB, fminf(WE2 + leC, leE2));

            float Dlu = Dl[sel][r];          // D_r[chunk_left-1]
            float Dlv = Dl[sel][r + 1];      // D_{r+1}[chunk_left-1]
            float u_in = fminf(Dlu + xA, xE1);
            float v_in = fminf(Dlu + xB, fminf(Dlv + xC, xE2));

            // parallel apply
            float u[4], v[4];
#pragma unroll
            for (int k = 0; k < 4; k++) {
                u[k] = fminf(u_in + pA[k], pE1[k]);
                v[k] = fminf(u_in + pB[k], fminf(v_in + pC[k], pE2[k]));
            }

            dlc = Dlv;                        // next phase top-row diag (tid 0)
            if (tid == DTH - 1) {
                Dl[sel ^ 1][r]     = u[3];    // boundaries for next chunk
                Dl[sel ^ 1][r + 1] = v[3];
            }
            if (r == BR - 2) {
                if (b < NB - 1)
                    *(float4*)(&g_row[b][colbase]) =
                        make_float4(v[0], v[1], v[2], v[3]);
                res = v[3];
            }
            sh_bound[tid] = v[3];
#pragma unroll
            for (int k = 0; k < 4; k++) Dp[k] = v[k];
            ca = ca2; cb = cb2;
            __syncthreads();
        }

        if (b < NB - 1) {
            __threadfence();
            if (tid == 0)
                asm volatile("st.release.gpu.global.u32 [%0], %1;"
                             :: "l"(&g_flag[b][j]), "r"(1u));
        }
    }

    if (b == NB - 1 && tid == DTH - 1) out[0] = res;
}

// ---------------------------------------------------------------------------
extern "C" void kernel_launch(void* const* d_in, const int* in_sizes, int n_in,
                              void* d_out, int out_size) {
    const float* kern = (const float*)d_in[0];
    const float* x    = (const float*)d_in[1];
    if (n_in >= 2 && in_sizes[0] == I_LEN * DIM && in_sizes[1] == K_LEN * DIM) {
        kern = (const float*)d_in[1];
        x    = (const float*)d_in[0];
    }

    int nwarp_rows = K_LEN + I_LEN;
    norms_kernel<<<(nwarp_rows + 7) / 8, 256>>>(kern, x);

    dim3 grid(I_LEN / BN, K_LEN / BM);
    cost_gemm<<<grid, 256>>>(kern, x);

    dtw_wave<<<NB, DTH>>>((float*)d_out, out_size);
}